// round 14
// baseline (speedup 1.0000x reference)
#include <cuda_runtime.h>
#include <cuda_bf16.h>
#include <math.h>
#include <cstdint>

#define BB 8
#define CC 64
#define OO 64
#define HH 96
#define WW 96
#define NN 9
#define HW (HH*WW)            // 9216
#define PIXELS (BB*HH*WW)     // 73728
#define SCR_CH 27

// offset (18) + modulation-raw (9) planes, layout [ch][pixel], bias included
__device__ float g_scr[SCR_CH * PIXELS];
// prepped B for deform: [tap][o(64)][k(128)] bf16, k = [whi(64) | wlo(64)]
__device__ __align__(16) unsigned short g_Bw[NN * 64 * 128];
// prepped B for offconv: [tap][o(32, 27 used)][k(128)] bf16, k = [whi | wlo]
__device__ __align__(16) unsigned short g_Bw2[NN * 32 * 128];

__device__ __forceinline__ void mma_bf16(float* d, const uint32_t* a,
                                         uint32_t b0, uint32_t b1) {
    asm volatile(
        "mma.sync.aligned.m16n8k16.row.col.f32.bf16.bf16.f32 "
        "{%0,%1,%2,%3}, {%4,%5,%6,%7}, {%8,%9}, {%0,%1,%2,%3};"
        : "+f"(d[0]), "+f"(d[1]), "+f"(d[2]), "+f"(d[3])
        : "r"(a[0]), "r"(a[1]), "r"(a[2]), "r"(a[3]), "r"(b0), "r"(b1));
}

__device__ __forceinline__ void ldmatrix_x4(uint32_t* r, uint32_t addr) {
    asm volatile(
        "ldmatrix.sync.aligned.m8n8.x4.shared.b16 {%0,%1,%2,%3}, [%4];"
        : "=r"(r[0]), "=r"(r[1]), "=r"(r[2]), "=r"(r[3]) : "r"(addr));
}
__device__ __forceinline__ void ldmatrix_x2(uint32_t& r0, uint32_t& r1,
                                            uint32_t addr) {
    asm volatile(
        "ldmatrix.sync.aligned.m8n8.x2.shared.b16 {%0,%1}, [%2];"
        : "=r"(r0), "=r"(r1) : "r"(addr));
}
__device__ __forceinline__ uint32_t smem_u32(const void* p) {
    uint32_t a;
    asm("{ .reg .u64 t; cvta.to.shared.u64 t, %1; cvt.u32.u64 %0, t; }"
        : "=r"(a) : "l"(p));
    return a;
}

// split two fp32 into packed bf16 hi + bf16 lo-residual
__device__ __forceinline__ void split2(float v0, float v1,
                                       uint32_t& hp, uint32_t& lp) {
    asm("cvt.rn.satfinite.bf16x2.f32 %0, %1, %2;" : "=r"(hp) : "f"(v1), "f"(v0));
    float h0 = __uint_as_float(hp << 16);
    float h1 = __uint_as_float(hp & 0xffff0000u);
    float l0 = v0 - h0, l1 = v1 - h1;
    asm("cvt.rn.satfinite.bf16x2.f32 %0, %1, %2;" : "=r"(lp) : "f"(l1), "f"(l0));
}

// ---------------------------------------------------------------------------
// Kernel P: build both B images (hi/lo split, both 128-wide [whi|wlo]).
// ---------------------------------------------------------------------------
__global__ void __launch_bounds__(256) k_prepw(
    const float* __restrict__ cw,
    const float* __restrict__ ow, const float* __restrict__ mw)
{
    int i = blockIdx.x * 256 + threadIdx.x;     // 432*256 = 110592
    if (i < NN * 64 * 128) {
        int n = i / (64 * 128);
        int rr = i % (64 * 128);
        int o = rr / 128;
        int k = rr % 128;
        int c = k & 63;
        float wv = cw[(o * CC + c) * NN + n];
        __nv_bfloat16 hi = __float2bfloat16(wv);
        __nv_bfloat16 val = (k < 64) ? hi
                          : __float2bfloat16(wv - __bfloat162float(hi));
        unsigned short u; memcpy(&u, &val, 2);
        g_Bw[i] = u;
    } else {
        int j = i - NN * 64 * 128;              // 9*32*128 = 36864
        int n = j / (32 * 128);
        int rr = j % (32 * 128);
        int o = rr / 128;
        int k = rr % 128;
        int c = k & 63;
        float wv = (o < 18) ? ow[(o * CC + c) * 9 + n]
                 : (o < 27) ? mw[((o - 18) * CC + c) * 9 + n] : 0.f;
        __nv_bfloat16 hi = __float2bfloat16(wv);
        __nv_bfloat16 val = (k < 64) ? hi
                          : __float2bfloat16(wv - __bfloat162float(hi));
        unsigned short u; memcpy(&u, &val, 2);
        g_Bw2[j] = u;
    }
}

#define AS2 136   // A row stride (68 words; mod 32 = 4 -> ldmatrix conflict-free)
#define BS2 136   // B row stride
#define ABUF (128 * AS2)   // elements per A buffer

// ---------------------------------------------------------------------------
// Kernel 1 (v14): offconv GEMM, 512-thr single-CTA/SM, double-buffered taps.
// 4 thr/pixel (16 ch each). Warp w: rows (w&3)*32, outputs (w>>2)*8.
// ---------------------------------------------------------------------------
__global__ void __launch_bounds__(512, 1) k_offconv_mma(
    const float* __restrict__ x,
    const float* __restrict__ ob, const float* __restrict__ mb)
{
    extern __shared__ unsigned short sm[];
    const int BBUF = 32 * BS2;
    unsigned short* A0 = sm;                  // 2 x 34816 B
    unsigned short* B0 = sm + 2 * ABUF;       // 2 x 8704 B

    const int tid = threadIdx.x;
    const int wid = tid >> 5;
    const int lane = tid & 31;
    const int g = lane >> 2;
    const int q = lane & 3;

    const int pxl = tid & 127;
    const int cq = tid >> 7;                  // channel quarter 0..3
    const int p = blockIdx.x * 128 + pxl;
    const int b = p / HW, r = p % HW;
    const int h = r / WW, w = r % WW;
    const float* xg = x + ((size_t)b * CC + cq * 16) * HW;

    const uint32_t asm_b = smem_u32(A0);
    const uint32_t bsm_b = smem_u32(B0);
    const uint32_t AOFF = ABUF * 2, BOFF = BBUF * 2;   // bytes
    const int tA = lane >> 3, riA = lane & 7;
    const int rowsBase = (wid & 3) * 32;
    const int og = wid >> 2;                  // output group of 8
    uint32_t aAddr[2];
    #pragma unroll
    for (int mt = 0; mt < 2; mt++) {
        int row = rowsBase + mt * 16 + (tA & 1) * 8 + riA;
        aAddr[mt] = asm_b + (uint32_t)(row * AS2 + (tA >> 1) * 8) * 2;
    }
    const int l16 = lane & 15;
    const int tB = l16 >> 3, riB = l16 & 7;
    uint32_t bAddr0 = bsm_b + (uint32_t)((og * 8 + riB) * BS2 + tB * 8) * 2;

    float acc[2][4];
    #pragma unroll
    for (int mt = 0; mt < 2; mt++)
        #pragma unroll
        for (int e = 0; e < 4; e++) acc[mt][e] = 0.f;

    auto fillB = [&](int n, int buf) {
        unsigned short* Bb = B0 + buf * BBUF;
        const uint4* src = (const uint4*)(g_Bw2 + n * 32 * 128);
        int i = tid;   // 512 uint4, 1 per thread
        int row = i >> 4, c4 = i & 15;
        ((uint4*)(Bb + row * BS2))[c4] = __ldg(src + i);
    };

    auto gatherA = [&](int n, int buf) {
        int dh = n / 3 - 1, dw = n % 3 - 1;
        int ih = h + dh, iw = w + dw;
        int off = ((unsigned)ih < HH && (unsigned)iw < WW) ? ih * WW + iw : -1;
        const float* xs = xg + off;
        uint2* arow = (uint2*)(A0 + buf * ABUF + pxl * AS2);
        if (off >= 0) {
            #pragma unroll
            for (int it = 0; it < 4; it++) {
                float t0 = __ldg(xs + (size_t)(4 * it) * HW);
                float t1 = __ldg(xs + (size_t)(4 * it + 1) * HW);
                float t2 = __ldg(xs + (size_t)(4 * it + 2) * HW);
                float t3 = __ldg(xs + (size_t)(4 * it + 3) * HW);
                uint32_t hp0, lp0, hp1, lp1;
                split2(t0, t1, hp0, lp0);
                split2(t2, t3, hp1, lp1);
                arow[cq * 4 + it]      = make_uint2(hp0, hp1);
                arow[16 + cq * 4 + it] = make_uint2(lp0, lp1);
            }
        } else {
            #pragma unroll
            for (int it = 0; it < 4; it++) {
                arow[cq * 4 + it]      = make_uint2(0u, 0u);
                arow[16 + cq * 4 + it] = make_uint2(0u, 0u);
            }
        }
    };

    fillB(0, 0);
    gatherA(0, 0);
    __syncthreads();

    #pragma unroll 1
    for (int n = 0; n < NN; n++) {
        int cur = n & 1;
        if (n + 1 < NN) { fillB(n + 1, cur ^ 1); gatherA(n + 1, cur ^ 1); }

        uint32_t aO = cur ? AOFF : 0u;
        uint32_t bO = cur ? BOFF : 0u;
        #pragma unroll
        for (int s = 0; s < 12; s++) {
            const int s3 = (s & 3) * 16;
            const int ka = s3 + ((s >= 4 && s < 8) ? 64 : 0);
            const int kb = s3 + ((s >= 8) ? 64 : 0);
            uint32_t a[2][4];
            ldmatrix_x4(a[0], aAddr[0] + aO + ka * 2);
            ldmatrix_x4(a[1], aAddr[1] + aO + ka * 2);
            uint32_t b0, b1;
            ldmatrix_x2(b0, b1, bAddr0 + bO + kb * 2);
            mma_bf16(acc[0], a[0], b0, b1);
            mma_bf16(acc[1], a[1], b0, b1);
        }
        __syncthreads();
    }

    // ---- epilogue -> g_scr[oc][pixel] (+bias), oc < 27 ----
    #pragma unroll
    for (int mt = 0; mt < 2; mt++) {
        int prow = blockIdx.x * 128 + rowsBase + mt * 16 + g;
        int oc = og * 8 + q * 2;
        if (oc < 27) {
            float bias = (oc < 18) ? ob[oc] : mb[oc - 18];
            g_scr[(size_t)oc * PIXELS + prow]     = acc[mt][0] + bias;
            g_scr[(size_t)oc * PIXELS + prow + 8] = acc[mt][2] + bias;
        }
        if (oc + 1 < 27) {
            float bias = (oc + 1 < 18) ? ob[oc + 1] : mb[oc - 17];
            g_scr[(size_t)(oc + 1) * PIXELS + prow]     = acc[mt][1] + bias;
            g_scr[(size_t)(oc + 1) * PIXELS + prow + 8] = acc[mt][3] + bias;
        }
    }
}

// ---------------------------------------------------------------------------
// Kernel 2 (v14): deform GEMM, 512-thr single-CTA/SM, double-buffered taps.
// 4 thr/pixel (16 ch each). Warp w: rows (w&3)*32, outputs (w>>2)*16.
// smem 104 KB x 1 CTA -> L1D ~124 KB, caches the 75 KB x-window.
// ---------------------------------------------------------------------------
__global__ void __launch_bounds__(512, 1) k_deform_mma(
    const float* __restrict__ x, const float* __restrict__ cb,
    float* __restrict__ out)
{
    extern __shared__ unsigned short sm[];
    const int BBUF = 64 * BS2;
    unsigned short* A0 = sm;                  // 2 x 34816 B
    unsigned short* B0 = sm + 2 * ABUF;       // 2 x 17408 B

    const int tid = threadIdx.x;
    const int wid = tid >> 5;
    const int lane = tid & 31;
    const int g = lane >> 2;
    const int q = lane & 3;

    const int pxl = tid & 127;
    const int cq = tid >> 7;                  // channel quarter 0..3
    const int p = blockIdx.x * 128 + pxl;
    const int b = p / HW, r = p % HW;
    const int h = r / WW, w = r % WW;
    const float* xg = x + ((size_t)b * CC + cq * 16) * HW;

    const uint32_t asm_b = smem_u32(A0);
    const uint32_t bsm_b = smem_u32(B0);
    const uint32_t AOFF = ABUF * 2, BOFF = BBUF * 2;   // bytes
    const int tA = lane >> 3, riA = lane & 7;
    const int rowsBase = (wid & 3) * 32;
    const int og = wid >> 2;                  // output group of 16
    uint32_t aAddr[2];
    #pragma unroll
    for (int mt = 0; mt < 2; mt++) {
        int row = rowsBase + mt * 16 + (tA & 1) * 8 + riA;
        aAddr[mt] = asm_b + (uint32_t)(row * AS2 + (tA >> 1) * 8) * 2;
    }
    const int l16 = lane & 15;
    const int tB = l16 >> 3, riB = l16 & 7;
    uint32_t bAddr[2];
    #pragma unroll
    for (int nt = 0; nt < 2; nt++) {
        int row = (og * 2 + nt) * 8 + riB;
        bAddr[nt] = bsm_b + (uint32_t)(row * BS2 + tB * 8) * 2;
    }

    float acc[2][2][4];
    #pragma unroll
    for (int mt = 0; mt < 2; mt++)
        #pragma unroll
        for (int nt = 0; nt < 2; nt++)
            #pragma unroll
            for (int e = 0; e < 4; e++) acc[mt][nt][e] = 0.f;

    auto fillB = [&](int n, int buf) {
        unsigned short* Bb = B0 + buf * BBUF;
        const uint4* src = (const uint4*)(g_Bw + n * 64 * 128);
        #pragma unroll
        for (int j = 0; j < 2; j++) {
            int i = tid + 512 * j;   // 1024 uint4, 2 per thread
            int row = i >> 4, c4 = i & 15;
            ((uint4*)(Bb + row * BS2))[c4] = __ldg(src + i);
        }
    };

    auto gatherA = [&](int n, int buf) {
        float offx = g_scr[n * PIXELS + p];
        float offy = g_scr[(9 + n) * PIXELS + p];
        float mraw = g_scr[(18 + n) * PIXELS + p];
        float m = 1.f / (1.f + __expf(-mraw));

        float px = offx + (float)(h + 1) + (float)(n / 3 - 1);
        float py = offy + (float)(w + 1) + (float)(n % 3 - 1);

        float flx = floorf(px), fly = floorf(py);
        int tlx = max(min((int)flx, 97), 0);
        int brx = max(min((int)flx + 1, 97), 0);
        int tly = max(min((int)fly, 97), 0);
        int bry = max(min((int)fly + 1, 97), 0);
        float pcx = fminf(fmaxf(px, 0.f), 97.f);
        float pcy = fminf(fmaxf(py, 0.f), 97.f);

        float axt = 1.f + ((float)tlx - pcx);
        float axb = 1.f - ((float)brx - pcx);
        float ayt = 1.f + ((float)tly - pcy);
        float ayb = 1.f - ((float)bry - pcy);

        float c_tl = axt * ayt * m;
        float c_tr = axt * ayb * m;
        float c_bl = axb * ayt * m;
        float c_br = axb * ayb * m;

        bool vtx = (tlx >= 1 && tlx <= 96);
        bool vbx = (brx >= 1 && brx <= 96);
        bool vty = (tly >= 1 && tly <= 96);
        bool vby = (bry >= 1 && bry <= 96);

        int a_tl = (tlx - 1) * WW + (tly - 1);
        int a_tr = (tlx - 1) * WW + (bry - 1);
        int a_bl = (brx - 1) * WW + (tly - 1);
        int a_br = (brx - 1) * WW + (bry - 1);
        if (!(vtx && vty)) { c_tl = 0.f; a_tl = 0; }
        if (!(vtx && vby)) { c_tr = 0.f; a_tr = 0; }
        if (!(vbx && vty)) { c_bl = 0.f; a_bl = 0; }
        if (!(vbx && vby)) { c_br = 0.f; a_br = 0; }

        uint2* arow = (uint2*)(A0 + buf * ABUF + pxl * AS2);
        #pragma unroll
        for (int it = 0; it < 4; it++) {
            const float* x0 = xg + (size_t)(4 * it) * HW;
            float t0 = c_tl * __ldg(x0 + a_tl) + c_tr * __ldg(x0 + a_tr)
                     + c_bl * __ldg(x0 + a_bl) + c_br * __ldg(x0 + a_br);
            const float* x1 = x0 + HW;
            float t1 = c_tl * __ldg(x1 + a_tl) + c_tr * __ldg(x1 + a_tr)
                     + c_bl * __ldg(x1 + a_bl) + c_br * __ldg(x1 + a_br);
            const float* x2 = x1 + HW;
            float t2 = c_tl * __ldg(x2 + a_tl) + c_tr * __ldg(x2 + a_tr)
                     + c_bl * __ldg(x2 + a_bl) + c_br * __ldg(x2 + a_br);
            const float* x3 = x2 + HW;
            float t3 = c_tl * __ldg(x3 + a_tl) + c_tr * __ldg(x3 + a_tr)
                     + c_bl * __ldg(x3 + a_bl) + c_br * __ldg(x3 + a_br);
            uint32_t hp0, lp0, hp1, lp1;
            split2(t0, t1, hp0, lp0);
            split2(t2, t3, hp1, lp1);
            arow[cq * 4 + it]      = make_uint2(hp0, hp1);
            arow[16 + cq * 4 + it] = make_uint2(lp0, lp1);
        }
    };

    fillB(0, 0);
    gatherA(0, 0);
    __syncthreads();

    #pragma unroll 1
    for (int n = 0; n < NN; n++) {
        int cur = n & 1;
        if (n + 1 < NN) { fillB(n + 1, cur ^ 1); gatherA(n + 1, cur ^ 1); }

        uint32_t aO = cur ? AOFF : 0u;
        uint32_t bO = cur ? BOFF : 0u;
        #pragma unroll
        for (int s = 0; s < 12; s++) {
            const int s3 = (s & 3) * 16;
            const int ka = s3 + ((s >= 4 && s < 8) ? 64 : 0);
            const int kb = s3 + ((s >= 8) ? 64 : 0);
            uint32_t a[2][4];
            ldmatrix_x4(a[0], aAddr[0] + aO + ka * 2);
            ldmatrix_x4(a[1], aAddr[1] + aO + ka * 2);
            #pragma unroll
            for (int nt = 0; nt < 2; nt++) {
                uint32_t b0, b1;
                ldmatrix_x2(b0, b1, bAddr[nt] + bO + kb * 2);
                mma_bf16(acc[0][nt], a[0], b0, b1);
                mma_bf16(acc[1][nt], a[1], b0, b1);
            }
        }
        __syncthreads();
    }

    // ---- epilogue ----
    #pragma unroll
    for (int mt = 0; mt < 2; mt++) {
        int prow = blockIdx.x * 128 + rowsBase + mt * 16 + g;
        int pb0 = prow / HW,       pr0 = prow % HW;
        int pb1 = (prow + 8) / HW, pr1 = (prow + 8) % HW;
        float* o0 = out + (size_t)pb0 * OO * HW + pr0;
        float* o1 = out + (size_t)pb1 * OO * HW + pr1;
        #pragma unroll
        for (int nt = 0; nt < 2; nt++) {
            int oc = og * 16 + nt * 8 + q * 2;
            float bb0 = cb[oc], bb1 = cb[oc + 1];
            o0[(size_t)oc * HW]       = acc[mt][nt][0] + bb0;
            o0[(size_t)(oc + 1) * HW] = acc[mt][nt][1] + bb1;
            o1[(size_t)oc * HW]       = acc[mt][nt][2] + bb0;
            o1[(size_t)(oc + 1) * HW] = acc[mt][nt][3] + bb1;
        }
    }
}

extern "C" void kernel_launch(void* const* d_in, const int* in_sizes, int n_in,
                              void* d_out, int out_size) {
    const float* x  = (const float*)d_in[0];
    const float* ow = (const float*)d_in[1];
    const float* ob = (const float*)d_in[2];
    const float* mw = (const float*)d_in[3];
    const float* mb = (const float*)d_in[4];
    const float* cw = (const float*)d_in[5];
    const float* cb = (const float*)d_in[6];
    float* out = (float*)d_out;

    const int smem1 = (2 * ABUF + 2 * 32 * BS2) * 2;   // 87040 B
    const int smem2 = (2 * ABUF + 2 * 64 * BS2) * 2;   // 104448 B
    cudaFuncSetAttribute(k_offconv_mma, cudaFuncAttributeMaxDynamicSharedMemorySize, smem1);
    cudaFuncSetAttribute(k_deform_mma,  cudaFuncAttributeMaxDynamicSharedMemorySize, smem2);

    k_prepw<<<432, 256>>>(cw, ow, mw);
    k_offconv_mma<<<PIXELS / 128, 512, smem1>>>(x, ob, mb);
    k_deform_mma<<<PIXELS / 128, 512, smem2>>>(x, cb, out);
}

// round 15
// speedup vs baseline: 1.2162x; 1.2162x over previous
#include <cuda_runtime.h>
#include <cuda_bf16.h>
#include <math.h>
#include <cstdint>

#define BB 8
#define CC 64
#define OO 64
#define HH 96
#define WW 96
#define NN 9
#define HW (HH*WW)            // 9216
#define PIXELS (BB*HH*WW)     // 73728

// prepped B for deform: [tap][o(64)][k(128)] bf16, k = [whi(64) | wlo(64)]
__device__ __align__(16) unsigned short g_Bw[NN * 64 * 128];
// prepped B for offconv: [tap][o(32, 27 used)][k(128)] bf16, k = [whi | wlo]
__device__ __align__(16) unsigned short g_Bw2[NN * 32 * 128];

__device__ __forceinline__ void mma_bf16(float* d, const uint32_t* a,
                                         uint32_t b0, uint32_t b1) {
    asm volatile(
        "mma.sync.aligned.m16n8k16.row.col.f32.bf16.bf16.f32 "
        "{%0,%1,%2,%3}, {%4,%5,%6,%7}, {%8,%9}, {%0,%1,%2,%3};"
        : "+f"(d[0]), "+f"(d[1]), "+f"(d[2]), "+f"(d[3])
        : "r"(a[0]), "r"(a[1]), "r"(a[2]), "r"(a[3]), "r"(b0), "r"(b1));
}

__device__ __forceinline__ void ldmatrix_x4(uint32_t* r, uint32_t addr) {
    asm volatile(
        "ldmatrix.sync.aligned.m8n8.x4.shared.b16 {%0,%1,%2,%3}, [%4];"
        : "=r"(r[0]), "=r"(r[1]), "=r"(r[2]), "=r"(r[3]) : "r"(addr));
}
__device__ __forceinline__ void ldmatrix_x2(uint32_t& r0, uint32_t& r1,
                                            uint32_t addr) {
    asm volatile(
        "ldmatrix.sync.aligned.m8n8.x2.shared.b16 {%0,%1}, [%2];"
        : "=r"(r0), "=r"(r1) : "r"(addr));
}
__device__ __forceinline__ uint32_t smem_u32(const void* p) {
    uint32_t a;
    asm("{ .reg .u64 t; cvta.to.shared.u64 t, %1; cvt.u32.u64 %0, t; }"
        : "=r"(a) : "l"(p));
    return a;
}

// split two fp32 into packed bf16 hi + bf16 lo-residual
__device__ __forceinline__ void split2(float v0, float v1,
                                       uint32_t& hp, uint32_t& lp) {
    asm("cvt.rn.satfinite.bf16x2.f32 %0, %1, %2;" : "=r"(hp) : "f"(v1), "f"(v0));
    float h0 = __uint_as_float(hp << 16);
    float h1 = __uint_as_float(hp & 0xffff0000u);
    float l0 = v0 - h0, l1 = v1 - h1;
    asm("cvt.rn.satfinite.bf16x2.f32 %0, %1, %2;" : "=r"(lp) : "f"(l1), "f"(l0));
}

// ---------------------------------------------------------------------------
// Kernel P: build both B images (hi/lo split, both 128-wide [whi|wlo]).
// ---------------------------------------------------------------------------
__global__ void __launch_bounds__(256) k_prepw(
    const float* __restrict__ cw,
    const float* __restrict__ ow, const float* __restrict__ mw)
{
    int i = blockIdx.x * 256 + threadIdx.x;     // 432*256 = 110592
    if (i < NN * 64 * 128) {
        int n = i / (64 * 128);
        int rr = i % (64 * 128);
        int o = rr / 128;
        int k = rr % 128;
        int c = k & 63;
        float wv = cw[(o * CC + c) * NN + n];
        __nv_bfloat16 hi = __float2bfloat16(wv);
        __nv_bfloat16 val = (k < 64) ? hi
                          : __float2bfloat16(wv - __bfloat162float(hi));
        unsigned short u; memcpy(&u, &val, 2);
        g_Bw[i] = u;
    } else {
        int j = i - NN * 64 * 128;              // 9*32*128 = 36864
        int n = j / (32 * 128);
        int rr = j % (32 * 128);
        int o = rr / 128;
        int k = rr % 128;
        int c = k & 63;
        float wv = (o < 18) ? ow[(o * CC + c) * 9 + n]
                 : (o < 27) ? mw[((o - 18) * CC + c) * 9 + n] : 0.f;
        __nv_bfloat16 hi = __float2bfloat16(wv);
        __nv_bfloat16 val = (k < 64) ? hi
                          : __float2bfloat16(wv - __bfloat162float(hi));
        unsigned short u; memcpy(&u, &val, 2);
        g_Bw2[j] = u;
    }
}

#define AS2 136   // A row stride (68 words; mod 32 = 4 -> ldmatrix conflict-free)
#define BS2 136   // B row stride
#define ABUF (128 * AS2)   // elements per A buffer
#define BBUF (64 * BS2)    // single B buffer (covers both phases)

// ---------------------------------------------------------------------------
// FUSED kernel (v15): per CTA of 128 pixels, 256 threads, 2 CTAs/SM.
// Phase 1: offconv GEMM -> 27 offset/mod planes in SMEM (no gmem round-trip).
// Phase 2: deform GEMM reading coords from SMEM, same MMA machinery.
// A double-buffered (big, latency-critical); B single-buffered (tiny fill,
// second per-tap barrier). smem = 2*34816 + 17408 + 13824 = 100864 B.
// ---------------------------------------------------------------------------
__global__ void __launch_bounds__(256, 2) k_fused(
    const float* __restrict__ x,
    const float* __restrict__ ob, const float* __restrict__ mb,
    const float* __restrict__ cb, float* __restrict__ out)
{
    extern __shared__ unsigned short sm[];
    unsigned short* A0 = sm;                  // 2 x 34816 B
    unsigned short* B0 = sm + 2 * ABUF;       // 1 x 17408 B
    float* scr = (float*)(sm + 2 * ABUF + BBUF);   // 27 x 128 fp32

    const int tid = threadIdx.x;
    const int wid = tid >> 5;
    const int lane = tid & 31;
    const int g = lane >> 2;
    const int q = lane & 3;

    const int pxl = tid & 127;
    const int chalf = tid >> 7;
    const int p = blockIdx.x * 128 + pxl;
    const int b = p / HW, r = p % HW;
    const int h = r / WW, w = r % WW;
    const float* xg = x + ((size_t)b * CC + chalf * 32) * HW;

    const uint32_t asm_b = smem_u32(A0);
    const uint32_t bsm_b = smem_u32(B0);
    const uint32_t AOFF = ABUF * 2;            // bytes between A buffers
    const int tA = lane >> 3, riA = lane & 7;
    const int rowsBase = (wid & 3) * 32;
    const int og = wid >> 2;                   // 0/1
    uint32_t aAddr[2];
    #pragma unroll
    for (int mt = 0; mt < 2; mt++) {
        int row = rowsBase + mt * 16 + (tA & 1) * 8 + riA;
        aAddr[mt] = asm_b + (uint32_t)(row * AS2 + (tA >> 1) * 8) * 2;
    }
    const int l16 = lane & 15;
    const int tB = l16 >> 3, riB = l16 & 7;
    uint32_t bAddr1[2];                         // phase 1: 32-row B
    #pragma unroll
    for (int nt = 0; nt < 2; nt++) {
        int row = (og * 2 + nt) * 8 + riB;
        bAddr1[nt] = bsm_b + (uint32_t)(row * BS2 + tB * 8) * 2;
    }
    uint32_t bAddr2[4];                         // phase 2: 64-row B
    #pragma unroll
    for (int nt = 0; nt < 4; nt++) {
        int row = (og * 4 + nt) * 8 + riB;
        bAddr2[nt] = bsm_b + (uint32_t)(row * BS2 + tB * 8) * 2;
    }

    // ======================= PHASE 1: offconv ============================
    {
        float acc[2][2][4];
        #pragma unroll
        for (int mt = 0; mt < 2; mt++)
            #pragma unroll
            for (int nt = 0; nt < 2; nt++)
                #pragma unroll
                for (int e = 0; e < 4; e++) acc[mt][nt][e] = 0.f;

        auto fillB1 = [&](int n) {
            const uint4* src = (const uint4*)(g_Bw2 + n * 32 * 128);
            #pragma unroll
            for (int j = 0; j < 2; j++) {
                int i = tid + 256 * j;     // 512 uint4
                int row = i >> 4, c4 = i & 15;
                ((uint4*)(B0 + row * BS2))[c4] = __ldg(src + i);
            }
        };
        auto gatherA1 = [&](int n, int buf) {
            int dh = n / 3 - 1, dw = n % 3 - 1;
            int ih = h + dh, iw = w + dw;
            int off = ((unsigned)ih < HH && (unsigned)iw < WW) ? ih * WW + iw : -1;
            const float* xs = xg + off;
            uint2* arow = (uint2*)(A0 + buf * ABUF + pxl * AS2);
            if (off >= 0) {
                #pragma unroll 2
                for (int it = 0; it < 8; it++) {
                    float t0 = __ldg(xs + (size_t)(4 * it) * HW);
                    float t1 = __ldg(xs + (size_t)(4 * it + 1) * HW);
                    float t2 = __ldg(xs + (size_t)(4 * it + 2) * HW);
                    float t3 = __ldg(xs + (size_t)(4 * it + 3) * HW);
                    uint32_t hp0, lp0, hp1, lp1;
                    split2(t0, t1, hp0, lp0);
                    split2(t2, t3, hp1, lp1);
                    arow[chalf * 8 + it]      = make_uint2(hp0, hp1);
                    arow[16 + chalf * 8 + it] = make_uint2(lp0, lp1);
                }
            } else {
                #pragma unroll
                for (int it = 0; it < 8; it++) {
                    arow[chalf * 8 + it]      = make_uint2(0u, 0u);
                    arow[16 + chalf * 8 + it] = make_uint2(0u, 0u);
                }
            }
        };

        fillB1(0);
        gatherA1(0, 0);
        __syncthreads();

        #pragma unroll 1
        for (int n = 0; n < NN; n++) {
            int cur = n & 1;
            if (n + 1 < NN) gatherA1(n + 1, cur ^ 1);

            uint32_t aO = cur ? AOFF : 0u;
            #pragma unroll
            for (int s = 0; s < 12; s++) {
                const int s3 = (s & 3) * 16;
                const int ka = s3 + ((s >= 4 && s < 8) ? 64 : 0);
                const int kb = s3 + ((s >= 8) ? 64 : 0);
                uint32_t a[2][4];
                ldmatrix_x4(a[0], aAddr[0] + aO + ka * 2);
                ldmatrix_x4(a[1], aAddr[1] + aO + ka * 2);
                #pragma unroll
                for (int nt = 0; nt < 2; nt++) {
                    uint32_t b0, b1;
                    ldmatrix_x2(b0, b1, bAddr1[nt] + kb * 2);
                    mma_bf16(acc[0][nt], a[0], b0, b1);
                    mma_bf16(acc[1][nt], a[1], b0, b1);
                }
            }
            __syncthreads();
            if (n + 1 < NN) { fillB1(n + 1); __syncthreads(); }
        }

        // epilogue -> scr[oc*128 + pxl_local] (+bias), oc < 27
        #pragma unroll
        for (int mt = 0; mt < 2; mt++) {
            int prl = rowsBase + mt * 16 + g;
            #pragma unroll
            for (int nt = 0; nt < 2; nt++) {
                int oc = og * 16 + nt * 8 + q * 2;
                if (oc < 27) {
                    float bias = (oc < 18) ? ob[oc] : mb[oc - 18];
                    scr[oc * 128 + prl]     = acc[mt][nt][0] + bias;
                    scr[oc * 128 + prl + 8] = acc[mt][nt][2] + bias;
                }
                if (oc + 1 < 27) {
                    float bias = (oc + 1 < 18) ? ob[oc + 1] : mb[oc - 17];
                    scr[(oc + 1) * 128 + prl]     = acc[mt][nt][1] + bias;
                    scr[(oc + 1) * 128 + prl + 8] = acc[mt][nt][3] + bias;
                }
            }
        }
    }
    __syncthreads();

    // ======================= PHASE 2: deform ============================
    {
        float acc[2][4][4];
        #pragma unroll
        for (int mt = 0; mt < 2; mt++)
            #pragma unroll
            for (int nt = 0; nt < 4; nt++)
                #pragma unroll
                for (int e = 0; e < 4; e++) acc[mt][nt][e] = 0.f;

        auto fillB2 = [&](int n) {
            const uint4* src = (const uint4*)(g_Bw + n * 64 * 128);
            #pragma unroll
            for (int j = 0; j < 4; j++) {
                int i = tid + 256 * j;     // 1024 uint4
                int row = i >> 4, c4 = i & 15;
                ((uint4*)(B0 + row * BS2))[c4] = __ldg(src + i);
            }
        };
        auto gatherA2 = [&](int n, int buf) {
            float offx = scr[n * 128 + pxl];
            float offy = scr[(9 + n) * 128 + pxl];
            float mraw = scr[(18 + n) * 128 + pxl];
            float m = 1.f / (1.f + __expf(-mraw));

            float px = offx + (float)(h + 1) + (float)(n / 3 - 1);
            float py = offy + (float)(w + 1) + (float)(n % 3 - 1);

            float flx = floorf(px), fly = floorf(py);
            int tlx = max(min((int)flx, 97), 0);
            int brx = max(min((int)flx + 1, 97), 0);
            int tly = max(min((int)fly, 97), 0);
            int bry = max(min((int)fly + 1, 97), 0);
            float pcx = fminf(fmaxf(px, 0.f), 97.f);
            float pcy = fminf(fmaxf(py, 0.f), 97.f);

            float axt = 1.f + ((float)tlx - pcx);
            float axb = 1.f - ((float)brx - pcx);
            float ayt = 1.f + ((float)tly - pcy);
            float ayb = 1.f - ((float)bry - pcy);

            float c_tl = axt * ayt * m;
            float c_tr = axt * ayb * m;
            float c_bl = axb * ayt * m;
            float c_br = axb * ayb * m;

            bool vtx = (tlx >= 1 && tlx <= 96);
            bool vbx = (brx >= 1 && brx <= 96);
            bool vty = (tly >= 1 && tly <= 96);
            bool vby = (bry >= 1 && bry <= 96);

            int a_tl = (tlx - 1) * WW + (tly - 1);
            int a_tr = (tlx - 1) * WW + (bry - 1);
            int a_bl = (brx - 1) * WW + (tly - 1);
            int a_br = (brx - 1) * WW + (bry - 1);
            if (!(vtx && vty)) { c_tl = 0.f; a_tl = 0; }
            if (!(vtx && vby)) { c_tr = 0.f; a_tr = 0; }
            if (!(vbx && vty)) { c_bl = 0.f; a_bl = 0; }
            if (!(vbx && vby)) { c_br = 0.f; a_br = 0; }

            uint2* arow = (uint2*)(A0 + buf * ABUF + pxl * AS2);
            #pragma unroll 2
            for (int it = 0; it < 8; it++) {
                const float* x0 = xg + (size_t)(4 * it) * HW;
                float t0 = c_tl * __ldg(x0 + a_tl) + c_tr * __ldg(x0 + a_tr)
                         + c_bl * __ldg(x0 + a_bl) + c_br * __ldg(x0 + a_br);
                const float* x1 = x0 + HW;
                float t1 = c_tl * __ldg(x1 + a_tl) + c_tr * __ldg(x1 + a_tr)
                         + c_bl * __ldg(x1 + a_bl) + c_br * __ldg(x1 + a_br);
                const float* x2 = x1 + HW;
                float t2 = c_tl * __ldg(x2 + a_tl) + c_tr * __ldg(x2 + a_tr)
                         + c_bl * __ldg(x2 + a_bl) + c_br * __ldg(x2 + a_br);
                const float* x3 = x2 + HW;
                float t3 = c_tl * __ldg(x3 + a_tl) + c_tr * __ldg(x3 + a_tr)
                         + c_bl * __ldg(x3 + a_bl) + c_br * __ldg(x3 + a_br);
                uint32_t hp0, lp0, hp1, lp1;
                split2(t0, t1, hp0, lp0);
                split2(t2, t3, hp1, lp1);
                arow[chalf * 8 + it]      = make_uint2(hp0, hp1);
                arow[16 + chalf * 8 + it] = make_uint2(lp0, lp1);
            }
        };

        fillB2(0);
        gatherA2(0, 0);
        __syncthreads();

        #pragma unroll 1
        for (int n = 0; n < NN; n++) {
            int cur = n & 1;
            if (n + 1 < NN) gatherA2(n + 1, cur ^ 1);

            uint32_t aO = cur ? AOFF : 0u;
            #pragma unroll
            for (int s = 0; s < 12; s++) {
                const int s3 = (s & 3) * 16;
                const int ka = s3 + ((s >= 4 && s < 8) ? 64 : 0);
                const int kb = s3 + ((s >= 8) ? 64 : 0);
                uint32_t a[2][4];
                ldmatrix_x4(a[0], aAddr[0] + aO + ka * 2);
                ldmatrix_x4(a[1], aAddr[1] + aO + ka * 2);
                #pragma unroll
                for (int nt = 0; nt < 4; nt++) {
                    uint32_t b0, b1;
                    ldmatrix_x2(b0, b1, bAddr2[nt] + kb * 2);
                    mma_bf16(acc[0][nt], a[0], b0, b1);
                    mma_bf16(acc[1][nt], a[1], b0, b1);
                }
            }
            __syncthreads();
            if (n + 1 < NN) { fillB2(n + 1); __syncthreads(); }
        }

        // ---- epilogue ----
        #pragma unroll
        for (int mt = 0; mt < 2; mt++) {
            int prow = blockIdx.x * 128 + rowsBase + mt * 16 + g;
            int pb0 = prow / HW,       pr0 = prow % HW;
            int pb1 = (prow + 8) / HW, pr1 = (prow + 8) % HW;
            float* o0 = out + (size_t)pb0 * OO * HW + pr0;
            float* o1 = out + (size_t)pb1 * OO * HW + pr1;
            #pragma unroll
            for (int nt = 0; nt < 4; nt++) {
                int oc = og * 32 + nt * 8 + q * 2;
                float bb0 = cb[oc], bb1 = cb[oc + 1];
                o0[(size_t)oc * HW]       = acc[mt][nt][0] + bb0;
                o0[(size_t)(oc + 1) * HW] = acc[mt][nt][1] + bb1;
                o1[(size_t)oc * HW]       = acc[mt][nt][2] + bb0;
                o1[(size_t)(oc + 1) * HW] = acc[mt][nt][3] + bb1;
            }
        }
    }
}

extern "C" void kernel_launch(void* const* d_in, const int* in_sizes, int n_in,
                              void* d_out, int out_size) {
    const float* x  = (const float*)d_in[0];
    const float* ow = (const float*)d_in[1];
    const float* ob = (const float*)d_in[2];
    const float* mw = (const float*)d_in[3];
    const float* mb = (const float*)d_in[4];
    const float* cw = (const float*)d_in[5];
    const float* cb = (const float*)d_in[6];
    float* out = (float*)d_out;

    const int smem = (2 * ABUF + BBUF) * 2 + 27 * 128 * 4;   // 100864 B
    cudaFuncSetAttribute(k_fused, cudaFuncAttributeMaxDynamicSharedMemorySize, smem);

    k_prepw<<<432, 256>>>(cw, ow, mw);
    k_fused<<<PIXELS / 128, 256, smem>>>(x, ob, mb, cb, out);
}

// round 16
// speedup vs baseline: 1.2712x; 1.0453x over previous
#include <cuda_runtime.h>
#include <cuda_bf16.h>
#include <math.h>
#include <cstdint>

#define BB 8
#define CC 64
#define OO 64
#define HH 96
#define WW 96
#define NN 9
#define HW (HH*WW)            // 9216
#define PIXELS (BB*HH*WW)     // 73728

// B fragment images (mma.sync per-lane register layout, bf16x2 words):
// deform : [n][kc(4)][set(2)][ntG(8)][lane(32)][r(2)]  -> 36864 uint32
// offconv: [n][kc(4)][set(2)][ntG(4)][lane(32)][r(2)]  -> 18432 uint32
__device__ __align__(16) uint32_t g_BwF [NN * 4096];
__device__ __align__(16) uint32_t g_BwF2[NN * 2048];

__device__ __forceinline__ void mma_bf16(float* d, const uint32_t* a,
                                         uint32_t b0, uint32_t b1) {
    asm volatile(
        "mma.sync.aligned.m16n8k16.row.col.f32.bf16.bf16.f32 "
        "{%0,%1,%2,%3}, {%4,%5,%6,%7}, {%8,%9}, {%0,%1,%2,%3};"
        : "+f"(d[0]), "+f"(d[1]), "+f"(d[2]), "+f"(d[3])
        : "r"(a[0]), "r"(a[1]), "r"(a[2]), "r"(a[3]), "r"(b0), "r"(b1));
}

__device__ __forceinline__ void ldmatrix_x4(uint32_t* r, uint32_t addr) {
    asm volatile(
        "ldmatrix.sync.aligned.m8n8.x4.shared.b16 {%0,%1,%2,%3}, [%4];"
        : "=r"(r[0]), "=r"(r[1]), "=r"(r[2]), "=r"(r[3]) : "r"(addr));
}
__device__ __forceinline__ uint32_t smem_u32(const void* p) {
    uint32_t a;
    asm("{ .reg .u64 t; cvta.to.shared.u64 t, %1; cvt.u32.u64 %0, t; }"
        : "=r"(a) : "l"(p));
    return a;
}

// split two fp32 into packed bf16 hi + bf16 lo-residual
__device__ __forceinline__ void split2(float v0, float v1,
                                       uint32_t& hp, uint32_t& lp) {
    asm("cvt.rn.satfinite.bf16x2.f32 %0, %1, %2;" : "=r"(hp) : "f"(v1), "f"(v0));
    float h0 = __uint_as_float(hp << 16);
    float h1 = __uint_as_float(hp & 0xffff0000u);
    float l0 = v0 - h0, l1 = v1 - h1;
    asm("cvt.rn.satfinite.bf16x2.f32 %0, %1, %2;" : "=r"(lp) : "f"(l1), "f"(l0));
}

__device__ __forceinline__ unsigned short bf16bits(float v) {
    __nv_bfloat16 b = __float2bfloat16(v);
    unsigned short u; memcpy(&u, &b, 2);
    return u;
}

// ---------------------------------------------------------------------------
// Kernel P: build B fragment images.
// Element (n, kc, set, ntG, lane, r): o = ntG*8 + lane/4,
//   c0 = kc*16 + (lane%4)*2 + r*8, c1 = c0+1
//   set 0 -> whi(c), set 1 -> wlo(c) = bf16(w - whi)
//   word = pack(val(c0) lo-half, val(c1) hi-half)
// ---------------------------------------------------------------------------
__global__ void __launch_bounds__(256) k_prepw(
    const float* __restrict__ cw,
    const float* __restrict__ ow, const float* __restrict__ mw)
{
    int i = blockIdx.x * 256 + threadIdx.x;     // 216*256 = 55296
    if (i < NN * 4096) {                        // deform image
        int r = i & 1, lane = (i >> 1) & 31, ntG = (i >> 6) & 7;
        int set = (i >> 9) & 1, kc = (i >> 10) & 3, n = i >> 12;
        int o = ntG * 8 + (lane >> 2);
        int c0 = kc * 16 + (lane & 3) * 2 + r * 8;
        float w0 = cw[(o * CC + c0) * NN + n];
        float w1 = cw[(o * CC + c0 + 1) * NN + n];
        unsigned short v0, v1;
        if (set == 0) { v0 = bf16bits(w0); v1 = bf16bits(w1); }
        else {
            float h0 = __bfloat162float(__float2bfloat16(w0));
            float h1 = __bfloat162float(__float2bfloat16(w1));
            v0 = bf16bits(w0 - h0); v1 = bf16bits(w1 - h1);
        }
        g_BwF[i] = (uint32_t)v0 | ((uint32_t)v1 << 16);
    } else {                                    // offconv image
        int j = i - NN * 4096;
        int r = j & 1, lane = (j >> 1) & 31, ntG = (j >> 6) & 3;
        int set = (j >> 8) & 1, kc = (j >> 9) & 3, n = j >> 11;
        int o = ntG * 8 + (lane >> 2);
        int c0 = kc * 16 + (lane & 3) * 2 + r * 8;
        float w0 = 0.f, w1 = 0.f;
        if (o < 18)      { w0 = ow[(o * CC + c0) * 9 + n];        w1 = ow[(o * CC + c0 + 1) * 9 + n]; }
        else if (o < 27) { w0 = mw[((o - 18) * CC + c0) * 9 + n]; w1 = mw[((o - 18) * CC + c0 + 1) * 9 + n]; }
        unsigned short v0, v1;
        if (set == 0) { v0 = bf16bits(w0); v1 = bf16bits(w1); }
        else {
            float h0 = __bfloat162float(__float2bfloat16(w0));
            float h1 = __bfloat162float(__float2bfloat16(w1));
            v0 = bf16bits(w0 - h0); v1 = bf16bits(w1 - h1);
        }
        g_BwF2[j] = (uint32_t)v0 | ((uint32_t)v1 << 16);
    }
}

#define AS2 136   // A row stride (68 words; mod 32 = 4 -> ldmatrix conflict-free)
#define ABUF (128 * AS2)   // elements per A buffer

// ---------------------------------------------------------------------------
// FUSED kernel (v16): 256 thr, 2 CTAs/SM. A double-buffered in smem;
// B fragments loaded directly from gmem (no B smem, 1 barrier per tap).
// Chunked MMA: per 16-ch chunk load A-hi/A-lo once, B-hi/B-lo once,
// compute hi*hi + lo*hi + hi*lo (A-frag wf 96->64, no redundant reloads).
// ---------------------------------------------------------------------------
__global__ void __launch_bounds__(256, 2) k_fused(
    const float* __restrict__ x,
    const float* __restrict__ ob, const float* __restrict__ mb,
    const float* __restrict__ cb, float* __restrict__ out)
{
    extern __shared__ unsigned short sm[];
    unsigned short* A0 = sm;                       // 2 x 34816 B
    float* scr = (float*)(sm + 2 * ABUF);          // 27 x 128 fp32

    const int tid = threadIdx.x;
    const int wid = tid >> 5;
    const int lane = tid & 31;
    const int g = lane >> 2;
    const int q = lane & 3;

    const int pxl = tid & 127;
    const int chalf = tid >> 7;
    const int p = blockIdx.x * 128 + pxl;
    const int b = p / HW, r = p % HW;
    const int h = r / WW, w = r % WW;
    const float* xg = x + ((size_t)b * CC + chalf * 32) * HW;

    const uint32_t asm_b = smem_u32(A0);
    const uint32_t AOFF = ABUF * 2;                // bytes between A buffers
    const int tA = lane >> 3, riA = lane & 7;
    const int rowsBase = (wid & 3) * 32;
    const int og = wid >> 2;                       // 0/1
    uint32_t aAddr[2];
    #pragma unroll
    for (int mt = 0; mt < 2; mt++) {
        int row = rowsBase + mt * 16 + (tA & 1) * 8 + riA;
        aAddr[mt] = asm_b + (uint32_t)(row * AS2 + (tA >> 1) * 8) * 2;
    }

    // ======================= PHASE 1: offconv ============================
    {
        float acc[2][2][4];
        #pragma unroll
        for (int mt = 0; mt < 2; mt++)
            #pragma unroll
            for (int nt = 0; nt < 2; nt++)
                #pragma unroll
                for (int e = 0; e < 4; e++) acc[mt][nt][e] = 0.f;

        auto gatherA1 = [&](int n, int buf) {
            int dh = n / 3 - 1, dw = n % 3 - 1;
            int ih = h + dh, iw = w + dw;
            int off = ((unsigned)ih < HH && (unsigned)iw < WW) ? ih * WW + iw : -1;
            const float* xs = xg + off;
            uint2* arow = (uint2*)(A0 + buf * ABUF + pxl * AS2);
            if (off >= 0) {
                #pragma unroll 2
                for (int it = 0; it < 8; it++) {
                    float t0 = __ldg(xs + (size_t)(4 * it) * HW);
                    float t1 = __ldg(xs + (size_t)(4 * it + 1) * HW);
                    float t2 = __ldg(xs + (size_t)(4 * it + 2) * HW);
                    float t3 = __ldg(xs + (size_t)(4 * it + 3) * HW);
                    uint32_t hp0, lp0, hp1, lp1;
                    split2(t0, t1, hp0, lp0);
                    split2(t2, t3, hp1, lp1);
                    arow[chalf * 8 + it]      = make_uint2(hp0, hp1);
                    arow[16 + chalf * 8 + it] = make_uint2(lp0, lp1);
                }
            } else {
                #pragma unroll
                for (int it = 0; it < 8; it++) {
                    arow[chalf * 8 + it]      = make_uint2(0u, 0u);
                    arow[16 + chalf * 8 + it] = make_uint2(0u, 0u);
                }
            }
        };

        gatherA1(0, 0);
        __syncthreads();

        #pragma unroll 1
        for (int n = 0; n < NN; n++) {
            int cur = n & 1;
            if (n + 1 < NN) gatherA1(n + 1, cur ^ 1);

            uint32_t aO = cur ? AOFF : 0u;
            const uint2* BF = (const uint2*)g_BwF2 + (size_t)n * 1024;
            #pragma unroll
            for (int kc = 0; kc < 4; kc++) {
                // B fragments (direct gmem, coalesced LDG.64)
                uint2 bh[2], bl[2];
                #pragma unroll
                for (int nt = 0; nt < 2; nt++) {
                    const uint2* bp = BF + ((kc * 2 + 0) * 4 + og * 2 + nt) * 32 + lane;
                    bh[nt] = __ldg(bp);
                    bl[nt] = __ldg(bp + 128);   // set 1 = +4*32 uint2
                }
                uint32_t ah[2][4], al[2][4];
                ldmatrix_x4(ah[0], aAddr[0] + aO + (kc * 16) * 2);
                ldmatrix_x4(ah[1], aAddr[1] + aO + (kc * 16) * 2);
                ldmatrix_x4(al[0], aAddr[0] + aO + (64 + kc * 16) * 2);
                ldmatrix_x4(al[1], aAddr[1] + aO + (64 + kc * 16) * 2);
                #pragma unroll
                for (int nt = 0; nt < 2; nt++) {
                    mma_bf16(acc[0][nt], ah[0], bh[nt].x, bh[nt].y);
                    mma_bf16(acc[1][nt], ah[1], bh[nt].x, bh[nt].y);
                    mma_bf16(acc[0][nt], al[0], bh[nt].x, bh[nt].y);
                    mma_bf16(acc[1][nt], al[1], bh[nt].x, bh[nt].y);
                    mma_bf16(acc[0][nt], ah[0], bl[nt].x, bl[nt].y);
                    mma_bf16(acc[1][nt], ah[1], bl[nt].x, bl[nt].y);
                }
            }
            __syncthreads();
        }

        // epilogue -> scr[oc*128 + pxl_local] (+bias), oc < 27
        #pragma unroll
        for (int mt = 0; mt < 2; mt++) {
            int prl = rowsBase + mt * 16 + g;
            #pragma unroll
            for (int nt = 0; nt < 2; nt++) {
                int oc = og * 16 + nt * 8 + q * 2;
                if (oc < 27) {
                    float bias = (oc < 18) ? ob[oc] : mb[oc - 18];
                    scr[oc * 128 + prl]     = acc[mt][nt][0] + bias;
                    scr[oc * 128 + prl + 8] = acc[mt][nt][2] + bias;
                }
                if (oc + 1 < 27) {
                    float bias = (oc + 1 < 18) ? ob[oc + 1] : mb[oc - 17];
                    scr[(oc + 1) * 128 + prl]     = acc[mt][nt][1] + bias;
                    scr[(oc + 1) * 128 + prl + 8] = acc[mt][nt][3] + bias;
                }
            }
        }
    }
    __syncthreads();

    // ======================= PHASE 2: deform ============================
    {
        float acc[2][4][4];
        #pragma unroll
        for (int mt = 0; mt < 2; mt++)
            #pragma unroll
            for (int nt = 0; nt < 4; nt++)
                #pragma unroll
                for (int e = 0; e < 4; e++) acc[mt][nt][e] = 0.f;

        auto gatherA2 = [&](int n, int buf) {
            float offx = scr[n * 128 + pxl];
            float offy = scr[(9 + n) * 128 + pxl];
            float mraw = scr[(18 + n) * 128 + pxl];
            float m = 1.f / (1.f + __expf(-mraw));

            float px = offx + (float)(h + 1) + (float)(n / 3 - 1);
            float py = offy + (float)(w + 1) + (float)(n % 3 - 1);

            float flx = floorf(px), fly = floorf(py);
            int tlx = max(min((int)flx, 97), 0);
            int brx = max(min((int)flx + 1, 97), 0);
            int tly = max(min((int)fly, 97), 0);
            int bry = max(min((int)fly + 1, 97), 0);
            float pcx = fminf(fmaxf(px, 0.f), 97.f);
            float pcy = fminf(fmaxf(py, 0.f), 97.f);

            float axt = 1.f + ((float)tlx - pcx);
            float axb = 1.f - ((float)brx - pcx);
            float ayt = 1.f + ((float)tly - pcy);
            float ayb = 1.f - ((float)bry - pcy);

            float c_tl = axt * ayt * m;
            float c_tr = axt * ayb * m;
            float c_bl = axb * ayt * m;
            float c_br = axb * ayb * m;

            bool vtx = (tlx >= 1 && tlx <= 96);
            bool vbx = (brx >= 1 && brx <= 96);
            bool vty = (tly >= 1 && tly <= 96);
            bool vby = (bry >= 1 && bry <= 96);

            int a_tl = (tlx - 1) * WW + (tly - 1);
            int a_tr = (tlx - 1) * WW + (bry - 1);
            int a_bl = (brx - 1) * WW + (tly - 1);
            int a_br = (brx - 1) * WW + (bry - 1);
            if (!(vtx && vty)) { c_tl = 0.f; a_tl = 0; }
            if (!(vtx && vby)) { c_tr = 0.f; a_tr = 0; }
            if (!(vbx && vty)) { c_bl = 0.f; a_bl = 0; }
            if (!(vbx && vby)) { c_br = 0.f; a_br = 0; }

            uint2* arow = (uint2*)(A0 + buf * ABUF + pxl * AS2);
            #pragma unroll 2
            for (int it = 0; it < 8; it++) {
                const float* x0 = xg + (size_t)(4 * it) * HW;
                float t0 = c_tl * __ldg(x0 + a_tl) + c_tr * __ldg(x0 + a_tr)
                         + c_bl * __ldg(x0 + a_bl) + c_br * __ldg(x0 + a_br);
                const float* x1 = x0 + HW;
                float t1 = c_tl * __ldg(x1 + a_tl) + c_tr * __ldg(x1 + a_tr)
                         + c_bl * __ldg(x1 + a_bl) + c_br * __ldg(x1 + a_br);
                const float* x2 = x1 + HW;
                float t2 = c_tl * __ldg(x2 + a_tl) + c_tr * __ldg(x2 + a_tr)
                         + c_bl * __ldg(x2 + a_bl) + c_br * __ldg(x2 + a_br);
                const float* x3 = x2 + HW;
                float t3 = c_tl * __ldg(x3 + a_tl) + c_tr * __ldg(x3 + a_tr)
                         + c_bl * __ldg(x3 + a_bl) + c_br * __ldg(x3 + a_br);
                uint32_t hp0, lp0, hp1, lp1;
                split2(t0, t1, hp0, lp0);
                split2(t2, t3, hp1, lp1);
                arow[chalf * 8 + it]      = make_uint2(hp0, hp1);
                arow[16 + chalf * 8 + it] = make_uint2(lp0, lp1);
            }
        };

        gatherA2(0, 0);
        __syncthreads();

        #pragma unroll 1
        for (int n = 0; n < NN; n++) {
            int cur = n & 1;
            if (n + 1 < NN) gatherA2(n + 1, cur ^ 1);

            uint32_t aO = cur ? AOFF : 0u;
            const uint2* BF = (const uint2*)g_BwF + (size_t)n * 2048;
            #pragma unroll
            for (int kc = 0; kc < 4; kc++) {
                uint2 bh[4], bl[4];
                #pragma unroll
                for (int nt = 0; nt < 4; nt++) {
                    const uint2* bp = BF + ((kc * 2 + 0) * 8 + og * 4 + nt) * 32 + lane;
                    bh[nt] = __ldg(bp);
                    bl[nt] = __ldg(bp + 256);   // set 1 = +8*32 uint2
                }
                uint32_t ah[2][4], al[2][4];
                ldmatrix_x4(ah[0], aAddr[0] + aO + (kc * 16) * 2);
                ldmatrix_x4(ah[1], aAddr[1] + aO + (kc * 16) * 2);
                ldmatrix_x4(al[0], aAddr[0] + aO + (64 + kc * 16) * 2);
                ldmatrix_x4(al[1], aAddr[1] + aO + (64 + kc * 16) * 2);
                #pragma unroll
                for (int nt = 0; nt < 4; nt++) {
                    mma_bf16(acc[0][nt], ah[0], bh[nt].x, bh[nt].y);
                    mma_bf16(acc[1][nt], ah[1], bh[nt].x, bh[nt].y);
                    mma_bf16(acc[0][nt], al[0], bh[nt].x, bh[nt].y);
                    mma_bf16(acc[1][nt], al[1], bh[nt].x, bh[nt].y);
                    mma_bf16(acc[0][nt], ah[0], bl[nt].x, bl[nt].y);
                    mma_bf16(acc[1][nt], ah[1], bl[nt].x, bl[nt].y);
                }
            }
            __syncthreads();
        }

        // ---- epilogue ----
        #pragma unroll
        for (int mt = 0; mt < 2; mt++) {
            int prow = blockIdx.x * 128 + rowsBase + mt * 16 + g;
            int pb0 = prow / HW,       pr0 = prow % HW;
            int pb1 = (prow + 8) / HW, pr1 = (prow + 8) % HW;
            float* o0 = out + (size_t)pb0 * OO * HW + pr0;
            float* o1 = out + (size_t)pb1 * OO * HW + pr1;
            #pragma unroll
            for (int nt = 0; nt < 4; nt++) {
                int oc = og * 32 + nt * 8 + q * 2;
                float bb0 = cb[oc], bb1 = cb[oc + 1];
                o0[(size_t)oc * HW]       = acc[mt][nt][0] + bb0;
                o0[(size_t)(oc + 1) * HW] = acc[mt][nt][1] + bb1;
                o1[(size_t)oc * HW]       = acc[mt][nt][2] + bb0;
                o1[(size_t)(oc + 1) * HW] = acc[mt][nt][3] + bb1;
            }
        }
    }
}

extern "C" void kernel_launch(void* const* d_in, const int* in_sizes, int n_in,
                              void* d_out, int out_size) {
    const float* x  = (const float*)d_in[0];
    const float* ow = (const float*)d_in[1];
    const float* ob = (const float*)d_in[2];
    const float* mw = (const float*)d_in[3];
    const float* mb = (const float*)d_in[4];
    const float* cw = (const float*)d_in[5];
    const float* cb = (const float*)d_in[6];
    float* out = (float*)d_out;

    const int smem = 2 * ABUF * 2 + 27 * 128 * 4;   // 83456 B
    cudaFuncSetAttribute(k_fused, cudaFuncAttributeMaxDynamicSharedMemorySize, smem);

    k_prepw<<<216, 256>>>(cw, ow, mw);
    k_fused<<<PIXELS / 128, 256, smem>>>(x, ob, mb, cb, out);
}

// round 17
// speedup vs baseline: 1.5382x; 1.2100x over previous
#include <cuda_runtime.h>
#include <cuda_fp16.h>
#include <math.h>
#include <cstdint>

#define BB 8
#define CC 64
#define OO 64
#define HH 96
#define WW 96
#define NN 9
#define HW (HH*WW)            // 9216
#define PIXELS (BB*HH*WW)     // 73728

// B fragment images (mma.sync per-lane register layout, fp16x2 words):
// deform : [n][kc(4)][set(2)][ntG(8)][lane(32)][r(2)]  -> 36864 uint32
// offconv: [n][kc(4)][set(2)][ntG(4)][lane(32)][r(2)]  -> 18432 uint32
__device__ __align__(16) uint32_t g_BwF [NN * 4096];
__device__ __align__(16) uint32_t g_BwF2[NN * 2048];

__device__ __forceinline__ void mma_f16(float* d, const uint32_t* a,
                                        uint32_t b0, uint32_t b1) {
    asm volatile(
        "mma.sync.aligned.m16n8k16.row.col.f32.f16.f16.f32 "
        "{%0,%1,%2,%3}, {%4,%5,%6,%7}, {%8,%9}, {%0,%1,%2,%3};"
        : "+f"(d[0]), "+f"(d[1]), "+f"(d[2]), "+f"(d[3])
        : "r"(a[0]), "r"(a[1]), "r"(a[2]), "r"(a[3]), "r"(b0), "r"(b1));
}

__device__ __forceinline__ void ldmatrix_x4(uint32_t* r, uint32_t addr) {
    asm volatile(
        "ldmatrix.sync.aligned.m8n8.x4.shared.b16 {%0,%1,%2,%3}, [%4];"
        : "=r"(r[0]), "=r"(r[1]), "=r"(r[2]), "=r"(r[3]) : "r"(addr));
}
__device__ __forceinline__ uint32_t smem_u32(const void* p) {
    uint32_t a;
    asm("{ .reg .u64 t; cvta.to.shared.u64 t, %1; cvt.u32.u64 %0, t; }"
        : "=r"(a) : "l"(p));
    return a;
}

// pack two fp32 into fp16x2 (lower = v0)
__device__ __forceinline__ uint32_t packh2(float v0, float v1) {
    uint32_t r;
    asm("cvt.rn.f16x2.f32 %0, %1, %2;" : "=r"(r) : "f"(v1), "f"(v0));
    return r;
}

__device__ __forceinline__ unsigned short f16bits(float v) {
    __half b = __float2half_rn(v);
    unsigned short u; memcpy(&u, &b, 2);
    return u;
}

// ---------------------------------------------------------------------------
// Kernel P: build B fragment images (fp16 hi + fp16 residual).
// Element (n, kc, set, ntG, lane, r): o = ntG*8 + lane/4,
//   c0 = kc*16 + (lane%4)*2 + r*8, c1 = c0+1
// ---------------------------------------------------------------------------
__global__ void __launch_bounds__(256) k_prepw(
    const float* __restrict__ cw,
    const float* __restrict__ ow, const float* __restrict__ mw)
{
    int i = blockIdx.x * 256 + threadIdx.x;     // 216*256 = 55296
    if (i < NN * 4096) {                        // deform image
        int r = i & 1, lane = (i >> 1) & 31, ntG = (i >> 6) & 7;
        int set = (i >> 9) & 1, kc = (i >> 10) & 3, n = i >> 12;
        int o = ntG * 8 + (lane >> 2);
        int c0 = kc * 16 + (lane & 3) * 2 + r * 8;
        float w0 = cw[(o * CC + c0) * NN + n];
        float w1 = cw[(o * CC + c0 + 1) * NN + n];
        unsigned short v0, v1;
        if (set == 0) { v0 = f16bits(w0); v1 = f16bits(w1); }
        else {
            float h0 = __half2float(__float2half_rn(w0));
            float h1 = __half2float(__float2half_rn(w1));
            v0 = f16bits(w0 - h0); v1 = f16bits(w1 - h1);
        }
        g_BwF[i] = (uint32_t)v0 | ((uint32_t)v1 << 16);
    } else {                                    // offconv image
        int j = i - NN * 4096;
        int r = j & 1, lane = (j >> 1) & 31, ntG = (j >> 6) & 3;
        int set = (j >> 8) & 1, kc = (j >> 9) & 3, n = j >> 11;
        int o = ntG * 8 + (lane >> 2);
        int c0 = kc * 16 + (lane & 3) * 2 + r * 8;
        float w0 = 0.f, w1 = 0.f;
        if (o < 18)      { w0 = ow[(o * CC + c0) * 9 + n];        w1 = ow[(o * CC + c0 + 1) * 9 + n]; }
        else if (o < 27) { w0 = mw[((o - 18) * CC + c0) * 9 + n]; w1 = mw[((o - 18) * CC + c0 + 1) * 9 + n]; }
        unsigned short v0, v1;
        if (set == 0) { v0 = f16bits(w0); v1 = f16bits(w1); }
        else {
            float h0 = __half2float(__float2half_rn(w0));
            float h1 = __half2float(__float2half_rn(w1));
            v0 = f16bits(w0 - h0); v1 = f16bits(w1 - h1);
        }
        g_BwF2[j] = (uint32_t)v0 | ((uint32_t)v1 << 16);
    }
}

#define AS3 72    // A row stride in fp16 (36 words; mod 32 = 4 -> ldmatrix ok)
#define ABUF (128 * AS3)   // halves per A buffer (18432 B)

// ---------------------------------------------------------------------------
// FUSED kernel (v17): fp16 2-term. 256 thr, 2 CTAs/SM.
// A (hi only) double-buffered in smem; B fragments (hi+lo) direct from gmem.
// Per 16-ch chunk: 2 ldmatrix.x4 (A), 2 B-sets, 2 MMA terms.
// ---------------------------------------------------------------------------
__global__ void __launch_bounds__(256, 2) k_fused(
    const float* __restrict__ x,
    const float* __restrict__ ob, const float* __restrict__ mb,
    const float* __restrict__ cb, float* __restrict__ out)
{
    extern __shared__ unsigned short sm[];
    unsigned short* A0 = sm;                       // 2 x 18432 B
    float* scr = (float*)(sm + 2 * ABUF);          // 27 x 128 fp32

    const int tid = threadIdx.x;
    const int wid = tid >> 5;
    const int lane = tid & 31;
    const int g = lane >> 2;
    const int q = lane & 3;

    const int pxl = tid & 127;
    const int chalf = tid >> 7;
    const int p = blockIdx.x * 128 + pxl;
    const int b = p / HW, r = p % HW;
    const int h = r / WW, w = r % WW;
    const float* xg = x + ((size_t)b * CC + chalf * 32) * HW;

    const uint32_t asm_b = smem_u32(A0);
    const uint32_t AOFF = ABUF * 2;                // bytes between A buffers
    const int tA = lane >> 3, riA = lane & 7;
    const int rowsBase = (wid & 3) * 32;
    const int og = wid >> 2;                       // 0/1
    uint32_t aAddr[2];
    #pragma unroll
    for (int mt = 0; mt < 2; mt++) {
        int row = rowsBase + mt * 16 + (tA & 1) * 8 + riA;
        aAddr[mt] = asm_b + (uint32_t)(row * AS3 + (tA >> 1) * 8) * 2;
    }

    // ======================= PHASE 1: offconv ============================
    {
        float acc[2][2][4];
        #pragma unroll
        for (int mt = 0; mt < 2; mt++)
            #pragma unroll
            for (int nt = 0; nt < 2; nt++)
                #pragma unroll
                for (int e = 0; e < 4; e++) acc[mt][nt][e] = 0.f;

        auto gatherA1 = [&](int n, int buf) {
            int dh = n / 3 - 1, dw = n % 3 - 1;
            int ih = h + dh, iw = w + dw;
            int off = ((unsigned)ih < HH && (unsigned)iw < WW) ? ih * WW + iw : -1;
            const float* xs = xg + off;
            uint2* arow = (uint2*)(A0 + buf * ABUF + pxl * AS3);
            if (off >= 0) {
                #pragma unroll 2
                for (int it = 0; it < 8; it++) {
                    float t0 = __ldg(xs + (size_t)(4 * it) * HW);
                    float t1 = __ldg(xs + (size_t)(4 * it + 1) * HW);
                    float t2 = __ldg(xs + (size_t)(4 * it + 2) * HW);
                    float t3 = __ldg(xs + (size_t)(4 * it + 3) * HW);
                    arow[chalf * 8 + it] = make_uint2(packh2(t0, t1), packh2(t2, t3));
                }
            } else {
                #pragma unroll
                for (int it = 0; it < 8; it++)
                    arow[chalf * 8 + it] = make_uint2(0u, 0u);
            }
        };

        gatherA1(0, 0);
        __syncthreads();

        #pragma unroll 1
        for (int n = 0; n < NN; n++) {
            int cur = n & 1;
            if (n + 1 < NN) gatherA1(n + 1, cur ^ 1);

            uint32_t aO = cur ? AOFF : 0u;
            const uint2* BF = (const uint2*)g_BwF2 + (size_t)n * 1024;
            #pragma unroll
            for (int kc = 0; kc < 4; kc++) {
                uint2 bh[2], bl[2];
                #pragma unroll
                for (int nt = 0; nt < 2; nt++) {
                    const uint2* bp = BF + ((kc * 2 + 0) * 4 + og * 2 + nt) * 32 + lane;
                    bh[nt] = __ldg(bp);
                    bl[nt] = __ldg(bp + 128);   // set 1 = +4*32 uint2
                }
                uint32_t ah[2][4];
                ldmatrix_x4(ah[0], aAddr[0] + aO + kc * 32);
                ldmatrix_x4(ah[1], aAddr[1] + aO + kc * 32);
                #pragma unroll
                for (int nt = 0; nt < 2; nt++) {
                    mma_f16(acc[0][nt], ah[0], bh[nt].x, bh[nt].y);
                    mma_f16(acc[1][nt], ah[1], bh[nt].x, bh[nt].y);
                    mma_f16(acc[0][nt], ah[0], bl[nt].x, bl[nt].y);
                    mma_f16(acc[1][nt], ah[1], bl[nt].x, bl[nt].y);
                }
            }
            __syncthreads();
        }

        // epilogue -> scr[oc*128 + pxl_local] (+bias), oc < 27
        #pragma unroll
        for (int mt = 0; mt < 2; mt++) {
            int prl = rowsBase + mt * 16 + g;
            #pragma unroll
            for (int nt = 0; nt < 2; nt++) {
                int oc = og * 16 + nt * 8 + q * 2;
                if (oc < 27) {
                    float bias = (oc < 18) ? ob[oc] : mb[oc - 18];
                    scr[oc * 128 + prl]     = acc[mt][nt][0] + bias;
                    scr[oc * 128 + prl + 8] = acc[mt][nt][2] + bias;
                }
                if (oc + 1 < 27) {
                    float bias = (oc + 1 < 18) ? ob[oc + 1] : mb[oc - 17];
                    scr[(oc + 1) * 128 + prl]     = acc[mt][nt][1] + bias;
                    scr[(oc + 1) * 128 + prl + 8] = acc[mt][nt][3] + bias;
                }
            }
        }
    }
    __syncthreads();

    // ======================= PHASE 2: deform ============================
    {
        float acc[2][4][4];
        #pragma unroll
        for (int mt = 0; mt < 2; mt++)
            #pragma unroll
            for (int nt = 0; nt < 4; nt++)
                #pragma unroll
                for (int e = 0; e < 4; e++) acc[mt][nt][e] = 0.f;

        auto gatherA2 = [&](int n, int buf) {
            float offx = scr[n * 128 + pxl];
            float offy = scr[(9 + n) * 128 + pxl];
            float mraw = scr[(18 + n) * 128 + pxl];
            float m = 1.f / (1.f + __expf(-mraw));

            float px = offx + (float)(h + 1) + (float)(n / 3 - 1);
            float py = offy + (float)(w + 1) + (float)(n % 3 - 1);

            float flx = floorf(px), fly = floorf(py);
            int tlx = max(min((int)flx, 97), 0);
            int brx = max(min((int)flx + 1, 97), 0);
            int tly = max(min((int)fly, 97), 0);
            int bry = max(min((int)fly + 1, 97), 0);
            float pcx = fminf(fmaxf(px, 0.f), 97.f);
            float pcy = fminf(fmaxf(py, 0.f), 97.f);

            float axt = 1.f + ((float)tlx - pcx);
            float axb = 1.f - ((float)brx - pcx);
            float ayt = 1.f + ((float)tly - pcy);
            float ayb = 1.f - ((float)bry - pcy);

            float c_tl = axt * ayt * m;
            float c_tr = axt * ayb * m;
            float c_bl = axb * ayt * m;
            float c_br = axb * ayb * m;

            bool vtx = (tlx >= 1 && tlx <= 96);
            bool vbx = (brx >= 1 && brx <= 96);
            bool vty = (tly >= 1 && tly <= 96);
            bool vby = (bry >= 1 && bry <= 96);

            int a_tl = (tlx - 1) * WW + (tly - 1);
            int a_tr = (tlx - 1) * WW + (bry - 1);
            int a_bl = (brx - 1) * WW + (tly - 1);
            int a_br = (brx - 1) * WW + (bry - 1);
            if (!(vtx && vty)) { c_tl = 0.f; a_tl = 0; }
            if (!(vtx && vby)) { c_tr = 0.f; a_tr = 0; }
            if (!(vbx && vty)) { c_bl = 0.f; a_bl = 0; }
            if (!(vbx && vby)) { c_br = 0.f; a_br = 0; }

            uint2* arow = (uint2*)(A0 + buf * ABUF + pxl * AS3);
            #pragma unroll 2
            for (int it = 0; it < 8; it++) {
                const float* x0 = xg + (size_t)(4 * it) * HW;
                float t0 = c_tl * __ldg(x0 + a_tl) + c_tr * __ldg(x0 + a_tr)
                         + c_bl * __ldg(x0 + a_bl) + c_br * __ldg(x0 + a_br);
                const float* x1 = x0 + HW;
                float t1 = c_tl * __ldg(x1 + a_tl) + c_tr * __ldg(x1 + a_tr)
                         + c_bl * __ldg(x1 + a_bl) + c_br * __ldg(x1 + a_br);
                const float* x2 = x1 + HW;
                float t2 = c_tl * __ldg(x2 + a_tl) + c_tr * __ldg(x2 + a_tr)
                         + c_bl * __ldg(x2 + a_bl) + c_br * __ldg(x2 + a_br);
                const float* x3 = x2 + HW;
                float t3 = c_tl * __ldg(x3 + a_tl) + c_tr * __ldg(x3 + a_tr)
                         + c_bl * __ldg(x3 + a_bl) + c_br * __ldg(x3 + a_br);
                arow[chalf * 8 + it] = make_uint2(packh2(t0, t1), packh2(t2, t3));
            }
        };

        gatherA2(0, 0);
        __syncthreads();

        #pragma unroll 1
        for (int n = 0; n < NN; n++) {
            int cur = n & 1;
            if (n + 1 < NN) gatherA2(n + 1, cur ^ 1);

            uint32_t aO = cur ? AOFF : 0u;
            const uint2* BF = (const uint2*)g_BwF + (size_t)n * 2048;
            #pragma unroll
            for (int kc = 0; kc < 4; kc++) {
                uint2 bh[4], bl[4];
                #pragma unroll
                for (int nt = 0; nt < 4; nt++) {
                    const uint2* bp = BF + ((kc * 2 + 0) * 8 + og * 4 + nt) * 32 + lane;
                    bh[nt] = __ldg(bp);
                    bl[nt] = __ldg(bp + 256);   // set 1 = +8*32 uint2
                }
                uint32_t ah[2][4];
                ldmatrix_x4(ah[0], aAddr[0] + aO + kc * 32);
                ldmatrix_x4(ah[1], aAddr[1] + aO + kc * 32);
                #pragma unroll
                for (int nt = 0; nt < 4; nt++) {
                    mma_f16(acc[0][nt], ah[0], bh[nt].x, bh[nt].y);
                    mma_f16(acc[1][nt], ah[1], bh[nt].x, bh[nt].y);
                    mma_f16(acc[0][nt], ah[0], bl[nt].x, bl[nt].y);
                    mma_f16(acc[1][nt], ah[1], bl[nt].x, bl[nt].y);
                }
            }
            __syncthreads();
        }

        // ---- epilogue ----
        #pragma unroll
        for (int mt = 0; mt < 2; mt++) {
            int prow = blockIdx.x * 128 + rowsBase + mt * 16 + g;
            int pb0 = prow / HW,       pr0 = prow % HW;
            int pb1 = (prow + 8) / HW, pr1 = (prow + 8) % HW;
            float* o0 = out + (size_t)pb0 * OO * HW + pr0;
            float* o1 = out + (size_t)pb1 * OO * HW + pr1;
            #pragma unroll
            for (int nt = 0; nt < 4; nt++) {
                int oc = og * 32 + nt * 8 + q * 2;
                float bb0 = cb[oc], bb1 = cb[oc + 1];
                o0[(size_t)oc * HW]       = acc[mt][nt][0] + bb0;
                o0[(size_t)(oc + 1) * HW] = acc[mt][nt][1] + bb1;
                o1[(size_t)oc * HW]       = acc[mt][nt][2] + bb0;
                o1[(size_t)(oc + 1) * HW] = acc[mt][nt][3] + bb1;
            }
        }
    }
}

extern "C" void kernel_launch(void* const* d_in, const int* in_sizes, int n_in,
                              void* d_out, int out_size) {
    const float* x  = (const float*)d_in[0];
    const float* ow = (const float*)d_in[1];
    const float* ob = (const float*)d_in[2];
    const float* mw = (const float*)d_in[3];
    const float* mb = (const float*)d_in[4];
    const float* cw = (const float*)d_in[5];
    const float* cb = (const float*)d_in[6];
    float* out = (float*)d_out;

    const int smem = 2 * ABUF * 2 + 27 * 128 * 4;   // 50688 B
    cudaFuncSetAttribute(k_fused, cudaFuncAttributeMaxDynamicSharedMemorySize, smem);

    k_prepw<<<216, 256>>>(cw, ow, mw);
    k_fused<<<PIXELS / 128, 256, smem>>>(x, ob, mb, cb, out);
}